// round 4
// baseline (speedup 1.0000x reference)
#include <cuda_runtime.h>
#include <cuda_fp16.h>

// LBP forward. out = 7.5 + 0.5 * sum_p 2^p * tanh(5*(samp_p - cen_p))
//
// Block = 128 threads = one (n,f) plane. tid -> (hb = tid>>4, wq = tid&15).
// Lanes wq in {14,15} are padding (dup lane-13 loads, no stores) so that each
// 16-lane group owns one row-block of HC=7 rows, and every shfl +/-1 that
// would cross a group/warp boundary lands on a lane already masked by the
// zero-pad edge condition (wq==0 for shfl_up, wq==13 for shfl_down).
//
// Per tap p the center plane and sample plane are the SAME channel c_p,
// shifted by (dy,dx) in {-1,0,1}^2: stream HC(+1) rows once, a rotating
// 1-row register buffer provides the dy=+/-1 partner, shfl provides dx=+/-1.

#define N_  32
#define D_  64
#define H_  56
#define W_  56
#define F_  128
#define P_  4
#define HW_ (H_ * W_)
#define HC_ 7            // rows per thread
#define WQ_ 14           // real float4 quads per row (lanes 14,15 pad)

__device__ __forceinline__ float2 tanh2_approx(float a, float b) {
    __half2 h = __floats2half2_rn(a, b);
    unsigned hin = *reinterpret_cast<unsigned*>(&h);
    unsigned hout;
    asm("tanh.approx.f16x2 %0, %1;" : "=r"(hout) : "r"(hin));
    __half2 r = *reinterpret_cast<__half2*>(&hout);
    return __half22float2(r);
}

// warp-uniform dx; edge lanes masked to the zero padding value.
__device__ __forceinline__ float4 shift4(float4 m, int dx, int wq) {
    if (dx == 0) return m;
    if (dx < 0) {
        float t = __shfl_up_sync(0xffffffffu, m.w, 1);
        return make_float4(wq > 0 ? t : 0.f, m.x, m.y, m.z);
    }
    float t = __shfl_down_sync(0xffffffffu, m.x, 1);
    return make_float4(m.y, m.z, m.w, (wq < WQ_ - 1) ? t : 0.f);
}

#define EMIT(j, cen, smp)                                                     \
    do {                                                                      \
        float2 t01 = tanh2_approx(((smp).x - (cen).x) * 5.f,                  \
                                  ((smp).y - (cen).y) * 5.f);                 \
        float2 t23 = tanh2_approx(((smp).z - (cen).z) * 5.f,                  \
                                  ((smp).w - (cen).w) * 5.f);                 \
        acc[j].x = fmaf(wp, t01.x, acc[j].x);                                 \
        acc[j].y = fmaf(wp, t01.y, acc[j].y);                                 \
        acc[j].z = fmaf(wp, t23.x, acc[j].z);                                 \
        acc[j].w = fmaf(wp, t23.y, acc[j].w);                                 \
    } while (0)

__global__ __launch_bounds__(128) void lbp_rows_kernel(
    const float* __restrict__ in,
    const int*   __restrict__ kern,   // (F,P,2)
    const int*   __restrict__ pm,     // (F,P)
    float*       __restrict__ out)
{
    int plane = blockIdx.x;           // n*F + f
    int f = plane & (F_ - 1);
    int n = plane >> 7;

    int tid = threadIdx.x;
    int hb  = tid >> 4;               // 0..7, 8 row-blocks of 7 rows
    int wq  = tid & 15;               // 0..15; 14,15 are padding lanes
    bool active = (wq < WQ_);
    int wqc = active ? wq : (WQ_ - 1);
    int h0 = hb * HC_;
    int w  = wqc * 4;

    const float* __restrict__ base = in + (size_t)n * D_ * HW_ + w;

    float4 acc[HC_];
#pragma unroll
    for (int j = 0; j < HC_; j++) acc[j] = make_float4(7.5f, 7.5f, 7.5f, 7.5f);

#pragma unroll
    for (int p = 0; p < P_; p++) {
        int c  = __ldg(&pm[f * P_ + p]);
        int dy = __ldg(&kern[(f * P_ + p) * 2 + 0]) - 1;
        int dx = __ldg(&kern[(f * P_ + p) * 2 + 1]) - 1;
        const float* __restrict__ pl = base + c * HW_ + h0 * W_;
        float wp = 0.5f * (float)(1 << p);

        if (dy == 0) {
#pragma unroll
            for (int j = 0; j < HC_; j++) {
                float4 m = *reinterpret_cast<const float4*>(pl + j * W_);
                float4 s = shift4(m, dx, wq);
                EMIT(j, m, s);
            }
        } else if (dy < 0) {
            // out row h: center row h, sample row h-1 (shifted)
            float4 sp;
            {
                float4 m = make_float4(0.f, 0.f, 0.f, 0.f);
                if (h0 > 0) m = *reinterpret_cast<const float4*>(pl - W_);
                sp = shift4(m, dx, wq);
            }
#pragma unroll
            for (int j = 0; j < HC_; j++) {
                float4 m = *reinterpret_cast<const float4*>(pl + j * W_);
                float4 s = shift4(m, dx, wq);
                EMIT(j, m, sp);
                sp = s;
            }
        } else {
            // out row h: center row h, sample row h+1 (shifted)
            float4 mp = *reinterpret_cast<const float4*>(pl);
#pragma unroll
            for (int j = 0; j < HC_; j++) {
                int r = h0 + j + 1;
                float4 m = make_float4(0.f, 0.f, 0.f, 0.f);
                if (r < H_) m = *reinterpret_cast<const float4*>(pl + (j + 1) * W_);
                float4 s = shift4(m, dx, wq);
                EMIT(j, mp, s);
                mp = m;
            }
        }
    }

    if (active) {
        float* o = out + (size_t)plane * HW_ + h0 * W_ + w;
#pragma unroll
        for (int j = 0; j < HC_; j++)
            *reinterpret_cast<float4*>(o + j * W_) = acc[j];
    }
}

extern "C" void kernel_launch(void* const* d_in, const int* in_sizes, int n_in,
                              void* d_out, int out_size)
{
    const float* in   = (const float*)d_in[0];
    const int*   kern = (const int*)d_in[1];
    const int*   pm   = (const int*)d_in[2];
    float*       out  = (float*)d_out;

    lbp_rows_kernel<<<N_ * F_, 128>>>(in, kern, pm, out);
}

// round 5
// speedup vs baseline: 1.2603x; 1.2603x over previous
#include <cuda_runtime.h>
#include <cuda_fp16.h>

// LBP forward: out[n,f,h,w] = sum_p 2^p * sigmoid((samp_p - cen_p)/0.1)
//            = 7.5 + 0.5 * sum_p 2^p * tanh(5*(samp_p - cen_p))
//
// Thread = (n, f, row-pair, wq): 8 outputs = rows {2rp, 2rp+1} x float4 quad.
// Per tap p, center and sample come from the SAME channel c_p shifted by
// (dy,dx) in {-1,0,1}^2:
//   dy=0 : sample rows == the two center regs (0 extra row loads)
//   dy=+-1: one row is shared with a center reg, one extra row load.
// dx=+-1 handled by one edge scalar per sample row + register select.
// Inner math: diff in f32 (no cancellation loss), then half2:
//   pack -> HMUL2(x5) -> tanh.approx.f16x2 -> HFMA2 accumulate, unpack once.

#define N_  32
#define D_  64
#define H_  56
#define W_  56
#define F_  128
#define P_  4
#define HW_ (H_ * W_)
#define WQ_ 14
#define RP_ 28
#define TOTAL_ (N_ * F_ * RP_ * WQ_)   // 1,605,632 threads

__device__ __forceinline__ __half2 tanh_h2(__half2 x) {
    unsigned v = *reinterpret_cast<unsigned*>(&x);
    asm("tanh.approx.f16x2 %0, %0;" : "+r"(v));
    return *reinterpret_cast<__half2*>(&v);
}

__device__ __forceinline__ void emit_h2(const float4& cen, const float4& smp,
                                        __half2 wp2, __half2& alo, __half2& ahi) {
    const __half2 five = __floats2half2_rn(5.f, 5.f);
    __half2 lo = __floats2half2_rn(smp.x - cen.x, smp.y - cen.y);
    __half2 hi = __floats2half2_rn(smp.z - cen.z, smp.w - cen.w);
    lo = tanh_h2(__hmul2(lo, five));
    hi = tanh_h2(__hmul2(hi, five));
    alo = __hfma2(wp2, lo, alo);
    ahi = __hfma2(wp2, hi, ahi);
}

__global__ __launch_bounds__(256) void lbp_pair_kernel(
    const float* __restrict__ in,
    const int*   __restrict__ kern,   // (F,P,2)
    const int*   __restrict__ pm,     // (F,P)
    float*       __restrict__ out)
{
    int idx = blockIdx.x * 256 + threadIdx.x;
    if (idx >= TOTAL_) return;

    int wq = idx % WQ_;
    int t  = idx / WQ_;
    int rp = t % RP_;
    t /= RP_;
    int f  = t & (F_ - 1);
    int n  = t >> 7;

    int r0 = rp * 2, r1 = r0 + 1;
    int w  = wq * 4;

    // all tap metadata in 3 vector loads
    int4 pmv = *reinterpret_cast<const int4*>(pm + f * P_);
    int4 k01 = *reinterpret_cast<const int4*>(kern + f * P_ * 2);      // p0(ky,kx) p1(ky,kx)
    int4 k23 = *reinterpret_cast<const int4*>(kern + f * P_ * 2 + 4);  // p2, p3
    int cs[4]  = {pmv.x, pmv.y, pmv.z, pmv.w};
    int dys[4] = {k01.x - 1, k01.z - 1, k23.x - 1, k23.z - 1};
    int dxs[4] = {k01.y - 1, k01.w - 1, k23.y - 1, k23.w - 1};

    const float* __restrict__ base = in + (size_t)n * D_ * HW_;

    __half2 z = __floats2half2_rn(0.f, 0.f);
    __half2 alo0 = z, ahi0 = z, alo1 = z, ahi1 = z;

#pragma unroll
    for (int p = 0; p < P_; p++) {
        const float* __restrict__ pl = base + cs[p] * HW_;
        const float* __restrict__ c0 = pl + r0 * W_ + w;

        float4 m0 = *reinterpret_cast<const float4*>(c0);
        float4 m1 = *reinterpret_cast<const float4*>(c0 + W_);

        int dy = dys[p], dx = dxs[p];
        int sr0 = r0 + dy, sr1 = r1 + dy;

        float4 s0, s1;
        if (dy == 0) {
            s0 = m0; s1 = m1;
        } else if (dy < 0) {
            s1 = m0;
            s0 = (sr0 >= 0) ? *reinterpret_cast<const float4*>(pl + sr0 * W_ + w)
                            : make_float4(0.f, 0.f, 0.f, 0.f);
        } else {
            s0 = m1;
            s1 = (sr1 < H_) ? *reinterpret_cast<const float4*>(pl + sr1 * W_ + w)
                            : make_float4(0.f, 0.f, 0.f, 0.f);
        }

        if (dx < 0) {
            float e0 = (w > 0 && sr0 >= 0 && sr0 < H_) ? __ldg(pl + sr0 * W_ + w - 1) : 0.f;
            float e1 = (w > 0 && sr1 >= 0 && sr1 < H_) ? __ldg(pl + sr1 * W_ + w - 1) : 0.f;
            s0 = make_float4(e0, s0.x, s0.y, s0.z);
            s1 = make_float4(e1, s1.x, s1.y, s1.z);
        } else if (dx > 0) {
            float e0 = (w + 4 < W_ && sr0 >= 0 && sr0 < H_) ? __ldg(pl + sr0 * W_ + w + 4) : 0.f;
            float e1 = (w + 4 < W_ && sr1 >= 0 && sr1 < H_) ? __ldg(pl + sr1 * W_ + w + 4) : 0.f;
            s0 = make_float4(s0.y, s0.z, s0.w, e0);
            s1 = make_float4(s1.y, s1.z, s1.w, e1);
        }

        __half2 wp2 = __floats2half2_rn(0.5f * (float)(1 << p), 0.5f * (float)(1 << p));
        emit_h2(m0, s0, wp2, alo0, ahi0);
        emit_h2(m1, s1, wp2, alo1, ahi1);
    }

    float* o = out + ((size_t)(n * F_ + f) * HW_ + r0 * W_ + w);
    float2 l0 = __half22float2(alo0), h0 = __half22float2(ahi0);
    float2 l1 = __half22float2(alo1), h1 = __half22float2(ahi1);
    *reinterpret_cast<float4*>(o) =
        make_float4(7.5f + l0.x, 7.5f + l0.y, 7.5f + h0.x, 7.5f + h0.y);
    *reinterpret_cast<float4*>(o + W_) =
        make_float4(7.5f + l1.x, 7.5f + l1.y, 7.5f + h1.x, 7.5f + h1.y);
}

extern "C" void kernel_launch(void* const* d_in, const int* in_sizes, int n_in,
                              void* d_out, int out_size)
{
    const float* in   = (const float*)d_in[0];
    const int*   kern = (const int*)d_in[1];
    const int*   pm   = (const int*)d_in[2];
    float*       out  = (float*)d_out;

    int blocks = (TOTAL_ + 255) / 256;   // 6272
    lbp_pair_kernel<<<blocks, 256>>>(in, kern, pm, out);
}